// round 13
// baseline (speedup 1.0000x reference)
#include <cuda_runtime.h>
#include <math.h>
#include <stdint.h>

#define NN    4096
#define DD    128
#define HH    2
#define DHH   64
#define FFD   256
#define NEE   2048
#define NNZZ  65536
#define SP    4           // attention key splits
#define LN_EPS 1e-5f

// ---------------- scratch (static device globals; no allocation) ----------------
__device__ float g_h [NN*DD];
__device__ float g_q [NN*DD];
__device__ float g_k [NN*DD];
__device__ float g_v [NN*DD];
__device__ float g_z [NN*FFD];
__device__ float g_xt[NN*DD];
__device__ float g_e [NEE*DD];
__device__ float g_pO[SP*NN*DD];      // unnormalized split outputs
__device__ float g_pl[SP*HH*NN];      // split row sums
// CSR scratch. cnt arrays are SELF-RESTORING: count adds each member once,
// fill subtracts each member once -> exactly 0 at the end of every call.
// (static init = 0 covers the first call; no zeroing kernel needed.)
__device__ int g_he_cnt[NEE];
__device__ int g_n_cnt [NN];
__device__ int g_he_off[NEE + 1];
__device__ int g_n_off [NN + 1];
__device__ int g_he_nodes[NNZZ];
__device__ int g_n_he    [NNZZ];

// ---------------- CSR build ----------------
// 4 edges per thread, coalesced batches, independent atomic chains
__global__ void count_kernel(const int* __restrict__ edge)
{
    int base = blockIdx.x * 1024 + threadIdx.x;
    int n0 = edge[base], n1 = edge[base + 256], n2 = edge[base + 512], n3 = edge[base + 768];
    int h0 = edge[NNZZ + base],       h1 = edge[NNZZ + base + 256];
    int h2 = edge[NNZZ + base + 512], h3 = edge[NNZZ + base + 768];
    atomicAdd(&g_n_cnt[n0], 1);  atomicAdd(&g_n_cnt[n1], 1);
    atomicAdd(&g_n_cnt[n2], 1);  atomicAdd(&g_n_cnt[n3], 1);
    atomicAdd(&g_he_cnt[h0], 1); atomicAdd(&g_he_cnt[h1], 1);
    atomicAdd(&g_he_cnt[h2], 1); atomicAdd(&g_he_cnt[h3], 1);
}

__global__ void __launch_bounds__(1024) scan_kernel()
{
    __shared__ int part[1024];
    const int* cnt = blockIdx.x == 0 ? g_he_cnt : g_n_cnt;
    int*       off = blockIdx.x == 0 ? g_he_off : g_n_off;
    const int  n   = blockIdx.x == 0 ? NEE : NN;
    const int  per = n / 1024;
    const int tid  = threadIdx.x;
    const int base = tid * per;

    int s = 0;
    for (int i = 0; i < per; i++) s += cnt[base + i];
    part[tid] = s;
    __syncthreads();
    for (int d = 1; d < 1024; d <<= 1) {
        int v = (tid >= d) ? part[tid - d] : 0;
        __syncthreads();
        part[tid] += v;
        __syncthreads();
    }
    int run = tid ? part[tid - 1] : 0;
    for (int i = 0; i < per; i++) { off[base + i] = run; run += cnt[base + i]; }
    if (tid == 1023) off[n] = run;
}

// decrement-fill: slot = off + (old_count - 1); cnt returns to 0 afterwards
__global__ void fill_kernel(const int* __restrict__ edge)
{
    int base = blockIdx.x * 1024 + threadIdx.x;
    int n0 = edge[base], n1 = edge[base + 256], n2 = edge[base + 512], n3 = edge[base + 768];
    int h0 = edge[NNZZ + base],       h1 = edge[NNZZ + base + 256];
    int h2 = edge[NNZZ + base + 512], h3 = edge[NNZZ + base + 768];

    int p0 = atomicAdd(&g_he_cnt[h0], -1);
    int p1 = atomicAdd(&g_he_cnt[h1], -1);
    int p2 = atomicAdd(&g_he_cnt[h2], -1);
    int p3 = atomicAdd(&g_he_cnt[h3], -1);
    int q0 = atomicAdd(&g_n_cnt[n0], -1);
    int q1 = atomicAdd(&g_n_cnt[n1], -1);
    int q2 = atomicAdd(&g_n_cnt[n2], -1);
    int q3 = atomicAdd(&g_n_cnt[n3], -1);

    g_he_nodes[g_he_off[h0] + p0 - 1] = n0;
    g_he_nodes[g_he_off[h1] + p1 - 1] = n1;
    g_he_nodes[g_he_off[h2] + p2 - 1] = n2;
    g_he_nodes[g_he_off[h3] + p3 - 1] = n3;
    g_n_he[g_n_off[n0] + q0 - 1] = h0;
    g_n_he[g_n_off[n1] + q1 - 1] = h1;
    g_n_he[g_n_off[n2] + q2 - 1] = h2;
    g_n_he[g_n_off[n3] + q3 - 1] = h3;
}

// ---------------- tf32 mma helpers ----------------
__device__ __forceinline__ uint32_t f2tf(float f)
{
    uint32_t r;
    asm("cvt.rna.tf32.f32 %0, %1;" : "=r"(r) : "f"(f));
    return r;
}

__device__ __forceinline__ void mma_tf32(float c[4], const uint32_t a[4],
                                         uint32_t b0, uint32_t b1)
{
    asm volatile(
        "mma.sync.aligned.m16n8k8.row.col.f32.tf32.tf32.f32 "
        "{%0,%1,%2,%3}, {%4,%5,%6,%7}, {%8,%9}, {%0,%1,%2,%3};"
        : "+f"(c[0]), "+f"(c[1]), "+f"(c[2]), "+f"(c[3])
        : "r"(a[0]), "r"(a[1]), "r"(a[2]), "r"(a[3]), "r"(b0), "r"(b1));
}

// ---------------- tf32 GEMM body: 32x64 tile, 4 warps (2x2), K-chunk 32 -------
#define APAD 36
#define BPAD 72

__device__ __forceinline__ void gemm_body(
    uint32_t* As, uint32_t* Bs,
    const float* __restrict__ A, const float* __restrict__ W,
    const float* __restrict__ bias, float* __restrict__ C,
    int K, int Nn, int mode)
{
    const int tid  = threadIdx.x;
    const int wid  = tid >> 5;
    const int lane = tid & 31;
    const int g    = lane >> 2;
    const int qr   = lane & 3;
    const int wr   = wid >> 1;
    const int wc   = wid & 1;
    const int m0   = blockIdx.y * 32;
    const int n0   = blockIdx.x * 64;
    const int row0 = m0 + wr * 16;
    const int cb   = wc * 32;

    const int ar0 = tid >> 3,  ac0 = tid & 7;
    const int ar1 = (tid + 128) >> 3, ac1 = (tid + 128) & 7;
    const int br0 = tid >> 4,  bc0 = tid & 15;
    const int br1 = (tid + 128) >> 4, bc1 = (tid + 128) & 15;
    const int br2 = (tid + 256) >> 4, bc2 = (tid + 256) & 15;
    const int br3 = (tid + 384) >> 4, bc3 = (tid + 384) & 15;

    float acc[4][4];
    #pragma unroll
    for (int nt = 0; nt < 4; nt++)
        #pragma unroll
        for (int i = 0; i < 4; i++) acc[nt][i] = 0.f;

    float4 ar[2], br[4];
    ar[0] = *(const float4*)&A[(m0 + ar0) * K + ac0 * 4];
    ar[1] = *(const float4*)&A[(m0 + ar1) * K + ac1 * 4];
    br[0] = *(const float4*)&W[br0 * Nn + n0 + bc0 * 4];
    br[1] = *(const float4*)&W[br1 * Nn + n0 + bc1 * 4];
    br[2] = *(const float4*)&W[br2 * Nn + n0 + bc2 * 4];
    br[3] = *(const float4*)&W[br3 * Nn + n0 + bc3 * 4];

    for (int k0 = 0; k0 < K; k0 += 32) {
        *(uint4*)&As[ar0 * APAD + ac0 * 4] =
            make_uint4(f2tf(ar[0].x), f2tf(ar[0].y), f2tf(ar[0].z), f2tf(ar[0].w));
        *(uint4*)&As[ar1 * APAD + ac1 * 4] =
            make_uint4(f2tf(ar[1].x), f2tf(ar[1].y), f2tf(ar[1].z), f2tf(ar[1].w));
        *(uint4*)&Bs[br0 * BPAD + bc0 * 4] =
            make_uint4(f2tf(br[0].x), f2tf(br[0].y), f2tf(br[0].z), f2tf(br[0].w));
        *(uint4*)&Bs[br1 * BPAD + bc1 * 4] =
            make_uint4(f2tf(br[1].x), f2tf(br[1].y), f2tf(br[1].z), f2tf(br[1].w));
        *(uint4*)&Bs[br2 * BPAD + bc2 * 4] =
            make_uint4(f2tf(br[2].x), f2tf(br[2].y), f2tf(br[2].z), f2tf(br[2].w));
        *(uint4*)&Bs[br3 * BPAD + bc3 * 4] =
            make_uint4(f2tf(br[3].x), f2tf(br[3].y), f2tf(br[3].z), f2tf(br[3].w));
        __syncthreads();

        if (k0 + 32 < K) {
            ar[0] = *(const float4*)&A[(m0 + ar0) * K + k0 + 32 + ac0 * 4];
            ar[1] = *(const float4*)&A[(m0 + ar1) * K + k0 + 32 + ac1 * 4];
            br[0] = *(const float4*)&W[(k0 + 32 + br0) * Nn + n0 + bc0 * 4];
            br[1] = *(const float4*)&W[(k0 + 32 + br1) * Nn + n0 + bc1 * 4];
            br[2] = *(const float4*)&W[(k0 + 32 + br2) * Nn + n0 + bc2 * 4];
            br[3] = *(const float4*)&W[(k0 + 32 + br3) * Nn + n0 + bc3 * 4];
        }

        #pragma unroll
        for (int kt = 0; kt < 4; kt++) {
            uint32_t a[4];
            a[0] = As[(wr * 16 + g    ) * APAD + kt * 8 + qr    ];
            a[1] = As[(wr * 16 + g + 8) * APAD + kt * 8 + qr    ];
            a[2] = As[(wr * 16 + g    ) * APAD + kt * 8 + qr + 4];
            a[3] = As[(wr * 16 + g + 8) * APAD + kt * 8 + qr + 4];
            #pragma unroll
            for (int nt = 0; nt < 4; nt++) {
                uint32_t b0 = Bs[(kt * 8 + qr    ) * BPAD + cb + nt * 8 + g];
                uint32_t b1 = Bs[(kt * 8 + qr + 4) * BPAD + cb + nt * 8 + g];
                mma_tf32(acc[nt], a, b0, b1);
            }
        }
        __syncthreads();
    }

    #pragma unroll
    for (int nt = 0; nt < 4; nt++) {
        int col = n0 + cb + nt * 8 + 2 * qr;
        float b0v = bias ? bias[col]     : 0.f;
        float b1v = bias ? bias[col + 1] : 0.f;
        float c0 = acc[nt][0] + b0v, c1 = acc[nt][1] + b1v;
        float c2 = acc[nt][2] + b0v, c3 = acc[nt][3] + b1v;
        if (mode == 1) {
            c0 = 1.f / (1.f + __expf(-c0));
            c1 = 1.f / (1.f + __expf(-c1));
            c2 = 1.f / (1.f + __expf(-c2));
            c3 = 1.f / (1.f + __expf(-c3));
        }
        *(float2*)&C[(row0 + g    ) * Nn + col] = make_float2(c0, c1);
        *(float2*)&C[(row0 + g + 8) * Nn + col] = make_float2(c2, c3);
    }
}

__global__ void __launch_bounds__(128)
gemm_mma_kernel(const float* __restrict__ A, const float* __restrict__ W,
                const float* __restrict__ bias, float* __restrict__ C,
                int K, int Nn, int mode)
{
    __shared__ uint32_t As[32 * APAD];
    __shared__ uint32_t Bs[32 * BPAD];
    gemm_body(As, Bs, A, W, bias, C, K, Nn, mode);
}

struct QKVArgs {
    const float* W[3];
    const float* b[3];
    float*       C[3];
};

__global__ void __launch_bounds__(128)
gemm_qkv_kernel(const float* __restrict__ A, QKVArgs args)
{
    __shared__ uint32_t As[32 * APAD];
    __shared__ uint32_t Bs[32 * BPAD];
    int z = blockIdx.z;
    gemm_body(As, Bs, A, args.W[z], args.b[z], args.C[z], DD, DD, 0);
}

// ---------------- GEMM fused with residual + LayerNorm -----------------------
// C[m,:] = LN(resid[m,:] + Aeff[m,:]@W + bias) * lng + lnb
// combine=1: Aeff = attention output assembled inline from g_pO/g_pl (K must be DD)
#define BPAD2 136
__global__ void __launch_bounds__(128)
gemm_ln_kernel(const float* __restrict__ A, const float* __restrict__ W,
               const float* __restrict__ bias, const float* __restrict__ resid,
               const float* __restrict__ lng, const float* __restrict__ lnb,
               float* __restrict__ C, int K, int combine)
{
    __shared__ uint32_t As[16 * APAD];
    __shared__ uint32_t Bs[32 * BPAD2];
    __shared__ float redS[16][4];
    __shared__ float redQ[16][4];

    const int tid  = threadIdx.x;
    const int wid  = tid >> 5;
    const int lane = tid & 31;
    const int g    = lane >> 2;
    const int qr   = lane & 3;
    const int m0   = blockIdx.x * 16;
    const int cb   = wid * 32;

    const int arow = tid >> 3, acol = tid & 7;
    const int aRow = m0 + arow;

    float inv_l[2] = {0.f, 0.f};
    if (combine) {
        #pragma unroll
        for (int h = 0; h < HH; h++) {
            float l = 0.f;
            #pragma unroll
            for (int s = 0; s < SP; s++) l += g_pl[(s * HH + h) * NN + aRow];
            inv_l[h] = 1.f / l;
        }
    }

    float acc[4][4];
    #pragma unroll
    for (int nt = 0; nt < 4; nt++)
        #pragma unroll
        for (int i = 0; i < 4; i++) acc[nt][i] = 0.f;

    float4 ar, br[8];
    #define LOAD_A(K0) do {                                              \
        int col = (K0) + acol * 4;                                       \
        if (combine) {                                                   \
            float4 o = make_float4(0.f, 0.f, 0.f, 0.f);                  \
            _Pragma("unroll")                                            \
            for (int s = 0; s < SP; s++) {                               \
                float4 p = *(const float4*)&g_pO[s * NN * DD + aRow * DD + col]; \
                o.x += p.x; o.y += p.y; o.z += p.z; o.w += p.w;          \
            }                                                            \
            float il = inv_l[col >> 6];                                  \
            ar = make_float4(o.x * il, o.y * il, o.z * il, o.w * il);    \
        } else {                                                         \
            ar = *(const float4*)&A[aRow * K + col];                     \
        }                                                                \
    } while (0)

    LOAD_A(0);
    #pragma unroll
    for (int it = 0; it < 8; it++) {
        int f = tid + it * 128;
        br[it] = *(const float4*)&W[(f >> 5) * DD + (f & 31) * 4];
    }

    for (int k0 = 0; k0 < K; k0 += 32) {
        *(uint4*)&As[arow * APAD + acol * 4] =
            make_uint4(f2tf(ar.x), f2tf(ar.y), f2tf(ar.z), f2tf(ar.w));
        #pragma unroll
        for (int it = 0; it < 8; it++) {
            int f = tid + it * 128;
            *(uint4*)&Bs[(f >> 5) * BPAD2 + (f & 31) * 4] =
                make_uint4(f2tf(br[it].x), f2tf(br[it].y), f2tf(br[it].z), f2tf(br[it].w));
        }
        __syncthreads();

        if (k0 + 32 < K) {
            LOAD_A(k0 + 32);
            #pragma unroll
            for (int it = 0; it < 8; it++) {
                int f = tid + it * 128;
                br[it] = *(const float4*)&W[(k0 + 32 + (f >> 5)) * DD + (f & 31) * 4];
            }
        }

        #pragma unroll
        for (int kt = 0; kt < 4; kt++) {
            uint32_t a[4];
            a[0] = As[(g    ) * APAD + kt * 8 + qr    ];
            a[1] = As[(g + 8) * APAD + kt * 8 + qr    ];
            a[2] = As[(g    ) * APAD + kt * 8 + qr + 4];
            a[3] = As[(g + 8) * APAD + kt * 8 + qr + 4];
            #pragma unroll
            for (int nt = 0; nt < 4; nt++) {
                uint32_t b0 = Bs[(kt * 8 + qr    ) * BPAD2 + cb + nt * 8 + g];
                uint32_t b1 = Bs[(kt * 8 + qr + 4) * BPAD2 + cb + nt * 8 + g];
                mma_tf32(acc[nt], a, b0, b1);
            }
        }
        __syncthreads();
    }

    float s_lo = 0.f, q_lo = 0.f, s_hi = 0.f, q_hi = 0.f;
    #pragma unroll
    for (int nt = 0; nt < 4; nt++) {
        int col = cb + nt * 8 + 2 * qr;
        float2 bv = *(const float2*)&bias[col];
        float2 r0 = *(const float2*)&resid[(m0 + g    ) * DD + col];
        float2 r1 = *(const float2*)&resid[(m0 + g + 8) * DD + col];
        float x0 = acc[nt][0] + bv.x + r0.x;
        float x1 = acc[nt][1] + bv.y + r0.y;
        float x2 = acc[nt][2] + bv.x + r1.x;
        float x3 = acc[nt][3] + bv.y + r1.y;
        acc[nt][0] = x0; acc[nt][1] = x1; acc[nt][2] = x2; acc[nt][3] = x3;
        s_lo += x0 + x1;  q_lo += x0 * x0 + x1 * x1;
        s_hi += x2 + x3;  q_hi += x2 * x2 + x3 * x3;
    }
    s_lo += __shfl_xor_sync(0xffffffffu, s_lo, 1);
    s_lo += __shfl_xor_sync(0xffffffffu, s_lo, 2);
    q_lo += __shfl_xor_sync(0xffffffffu, q_lo, 1);
    q_lo += __shfl_xor_sync(0xffffffffu, q_lo, 2);
    s_hi += __shfl_xor_sync(0xffffffffu, s_hi, 1);
    s_hi += __shfl_xor_sync(0xffffffffu, s_hi, 2);
    q_hi += __shfl_xor_sync(0xffffffffu, q_hi, 1);
    q_hi += __shfl_xor_sync(0xffffffffu, q_hi, 2);
    if (qr == 0) {
        redS[g][wid]     = s_lo;  redQ[g][wid]     = q_lo;
        redS[g + 8][wid] = s_hi;  redQ[g + 8][wid] = q_hi;
    }
    __syncthreads();

    float sl = redS[g][0] + redS[g][1] + redS[g][2] + redS[g][3];
    float ql = redQ[g][0] + redQ[g][1] + redQ[g][2] + redQ[g][3];
    float sh = redS[g + 8][0] + redS[g + 8][1] + redS[g + 8][2] + redS[g + 8][3];
    float qh = redQ[g + 8][0] + redQ[g + 8][1] + redQ[g + 8][2] + redQ[g + 8][3];
    float mean_lo = sl * (1.f / 128.f);
    float mean_hi = sh * (1.f / 128.f);
    float rstd_lo = rsqrtf(ql * (1.f / 128.f) - mean_lo * mean_lo + LN_EPS);
    float rstd_hi = rsqrtf(qh * (1.f / 128.f) - mean_hi * mean_hi + LN_EPS);

    #pragma unroll
    for (int nt = 0; nt < 4; nt++) {
        int col = cb + nt * 8 + 2 * qr;
        float2 gg = *(const float2*)&lng[col];
        float2 bb = *(const float2*)&lnb[col];
        float2 o0, o1;
        o0.x = (acc[nt][0] - mean_lo) * rstd_lo * gg.x + bb.x;
        o0.y = (acc[nt][1] - mean_lo) * rstd_lo * gg.y + bb.y;
        o1.x = (acc[nt][2] - mean_hi) * rstd_hi * gg.x + bb.x;
        o1.y = (acc[nt][3] - mean_hi) * rstd_hi * gg.y + bb.y;
        *(float2*)&C[(m0 + g    ) * DD + col] = o0;
        *(float2*)&C[(m0 + g + 8) * DD + col] = o1;
    }
}

// ---------------- tensor-core flash attention, split-K, 128 queries/CTA -------
// 8 warps, each owns 16 query rows across the full 64 key/output columns.
// K/V tiles double-buffered via register prefetch.
#define KPAD 68
#define VPAD 72
#define ATT_SMEM ((64*KPAD + 64*VPAD + 8*16*KPAD) * 4)   // 70656 bytes

__global__ void __launch_bounds__(256)
attn_mma_kernel(const float* __restrict__ q, const float* __restrict__ k,
                const float* __restrict__ v)
{
    extern __shared__ uint32_t smu[];
    uint32_t* Ks = smu;
    uint32_t* Vs = smu + 64 * KPAD;
    uint32_t* Ps = smu + 64 * KPAD + 64 * VPAD + (threadIdx.x >> 5) * (16 * KPAD);

    const int tid  = threadIdx.x;
    const int wid  = tid >> 5;
    const int lane = tid & 31;
    const int h    = blockIdx.y;
    const int s    = blockIdx.z;
    const int q0   = blockIdx.x * 128;
    const int g    = lane >> 2;
    const int qr   = lane & 3;
    const int base = h * DHH;
    const int row0 = q0 + wid * 16;
    const int kb   = s * (NN / SP);
    const int ke   = kb + (NN / SP);

    uint32_t qa[8][4];
    #pragma unroll
    for (int kt = 0; kt < 8; kt++) {
        qa[kt][0] = f2tf(q[(row0 + g    ) * DD + base + kt * 8 + qr    ] * 0.125f);
        qa[kt][1] = f2tf(q[(row0 + g + 8) * DD + base + kt * 8 + qr    ] * 0.125f);
        qa[kt][2] = f2tf(q[(row0 + g    ) * DD + base + kt * 8 + qr + 4] * 0.125f);
        qa[kt][3] = f2tf(q[(row0 + g + 8) * DD + base + kt * 8 + qr + 4] * 0.125f);
    }

    float oc[8][4];
    #pragma unroll
    for (int nt = 0; nt < 8; nt++)
        #pragma unroll
        for (int i = 0; i < 4; i++) oc[nt][i] = 0.f;
    float l_lo = 0.f, l_hi = 0.f;

    // prefetch registers for the double buffer
    const int ldrow = tid >> 4, ldc4 = tid & 15;     // + it*16 rows
    float4 kr[4], vr[4];
    #pragma unroll
    for (int it = 0; it < 4; it++) {
        kr[it] = *(const float4*)&k[(kb + ldrow + it * 16) * DD + base + ldc4 * 4];
        vr[it] = *(const float4*)&v[(kb + ldrow + it * 16) * DD + base + ldc4 * 4];
    }

    for (int j0 = kb; j0 < ke; j0 += 64) {
        #pragma unroll
        for (int it = 0; it < 4; it++) {
            int row = ldrow + it * 16;
            *(uint4*)&Ks[row * KPAD + ldc4 * 4] =
                make_uint4(f2tf(kr[it].x), f2tf(kr[it].y), f2tf(kr[it].z), f2tf(kr[it].w));
            *(uint4*)&Vs[row * VPAD + ldc4 * 4] =
                make_uint4(f2tf(vr[it].x), f2tf(vr[it].y), f2tf(vr[it].z), f2tf(vr[it].w));
        }
        __syncthreads();

        if (j0 + 64 < ke) {
            #pragma unroll
            for (int it = 0; it < 4; it++) {
                kr[it] = *(const float4*)&k[(j0 + 64 + ldrow + it * 16) * DD + base + ldc4 * 4];
                vr[it] = *(const float4*)&v[(j0 + 64 + ldrow + it * 16) * DD + base + ldc4 * 4];
            }
        }

        // S = Q @ K^T (16 x 64 per warp)
        float sc[8][4];
        #pragma unroll
        for (int nt = 0; nt < 8; nt++)
            #pragma unroll
            for (int i = 0; i < 4; i++) sc[nt][i] = 0.f;

        #pragma unroll
        for (int nt = 0; nt < 8; nt++) {
            #pragma unroll
            for (int kt = 0; kt < 8; kt++) {
                uint32_t b0 = Ks[(nt * 8 + g) * KPAD + kt * 8 + qr    ];
                uint32_t b1 = Ks[(nt * 8 + g) * KPAD + kt * 8 + qr + 4];
                mma_tf32(sc[nt], qa[kt], b0, b1);
            }
        }

        // P = exp(S); warp-local row sums; stash P in per-warp smem
        float s_lo = 0.f, s_hi = 0.f;
        #pragma unroll
        for (int nt = 0; nt < 8; nt++) {
            float e0 = __expf(sc[nt][0]), e1 = __expf(sc[nt][1]);
            float e2 = __expf(sc[nt][2]), e3 = __expf(sc[nt][3]);
            s_lo += e0 + e1;
            s_hi += e2 + e3;
            *(uint2*)&Ps[ g      * KPAD + nt * 8 + 2 * qr] = make_uint2(f2tf(e0), f2tf(e1));
            *(uint2*)&Ps[(g + 8) * KPAD + nt * 8 + 2 * qr] = make_uint2(f2tf(e2), f2tf(e3));
        }
        s_lo += __shfl_xor_sync(0xffffffffu, s_lo, 1);
        s_lo += __shfl_xor_sync(0xffffffffu, s_lo, 2);
        s_hi += __shfl_xor_sync(0xffffffffu, s_hi, 1);
        s_hi += __shfl_xor_sync(0xffffffffu, s_hi, 2);
        l_lo += s_lo;
        l_hi += s_hi;
        __syncwarp();

        // O += P @ V
        #pragma unroll
        for (int kt = 0; kt < 8; kt++) {
            uint32_t a[4];
            a[0] = Ps[ g      * KPAD + kt * 8 + qr    ];
            a[1] = Ps[(g + 8) * KPAD + kt * 8 + qr    ];
            a[2] = Ps[ g      * KPAD + kt * 8 + qr + 4];
            a[3] = Ps[(g + 8) * KPAD + kt * 8 + qr + 4];
            #pragma unroll
            for (int nt = 0; nt < 8; nt++) {
                uint32_t b0 = Vs[(kt * 8 + qr    ) * VPAD + nt * 8 + g];
                uint32_t b1 = Vs[(kt * 8 + qr + 4) * VPAD + nt * 8 + g];
                mma_tf32(oc[nt], a, b0, b1);
            }
        }
        __syncthreads();   // protect Ks/Vs before next store phase
    }

    if (qr == 0) {
        g_pl[(s * HH + h) * NN + row0 + g]     = l_lo;
        g_pl[(s * HH + h) * NN + row0 + g + 8] = l_hi;
    }

    float* pO = &g_pO[s * NN * DD];
    #pragma unroll
    for (int nt = 0; nt < 8; nt++) {
        *(float2*)&pO[(row0 + g    ) * DD + base + nt * 8 + 2 * qr] =
            make_float2(oc[nt][0], oc[nt][1]);
        *(float2*)&pO[(row0 + g + 8) * DD + base + nt * 8 + 2 * qr] =
            make_float2(oc[nt][2], oc[nt][3]);
    }
}

// ---------------- hypergraph gathers (atomic-free via CSR) --------------------
__global__ void __launch_bounds__(128)
gather_e_kernel(const float* __restrict__ xt)
{
    __shared__ int mem[128];
    const int he = blockIdx.x;
    const int d  = threadIdx.x;
    const int beg = g_he_off[he], end = g_he_off[he + 1];

    float s = 0.f;
    for (int base = beg; base < end; base += 128) {
        int cnt = min(128, end - base);
        __syncthreads();
        if (d < cnt) mem[d] = g_he_nodes[base + d];
        __syncthreads();
        for (int i = 0; i < cnt; i++) s += xt[mem[i] * DD + d];
    }
    float binv = (end > beg) ? 1.f / (float)(end - beg) : 0.f;
    g_e[he * DD + d] = s * binv;
}

__global__ void __launch_bounds__(128)
gather_out_kernel(float* __restrict__ out, const float* __restrict__ bh)
{
    __shared__ int mem[128];
    const int n = blockIdx.x;
    const int d = threadIdx.x;
    const int beg = g_n_off[n], end = g_n_off[n + 1];

    float s = 0.f;
    for (int base = beg; base < end; base += 128) {
        int cnt = min(128, end - base);
        __syncthreads();
        if (d < cnt) mem[d] = g_n_he[base + d];
        __syncthreads();
        for (int i = 0; i < cnt; i++) s += g_e[mem[i] * DD + d];
    }
    float dinv = (end > beg) ? 1.f / (float)(end - beg) : 0.f;
    out[n * DD + d] = fmaxf(s * dinv + bh[d], 0.f);
}

// ---------------- host ----------------
static inline void run_gemm(const float* A, const float* W, const float* bias, float* C,
                            int M, int K, int Nn, int mode)
{
    dim3 grid(Nn / 64, M / 32);
    gemm_mma_kernel<<<grid, 128>>>(A, W, bias, C, K, Nn, mode);
}

extern "C" void kernel_launch(void* const* d_in, const int* in_sizes, int n_in,
                              void* d_out, int out_size)
{
    const float* x    = (const float*)d_in[0];
    const int*   edge = (const int*)d_in[1];      // int32: JAX x64 disabled
    const float* Wq  = (const float*)d_in[2];   const float* bq  = (const float*)d_in[3];
    const float* Wk  = (const float*)d_in[4];   const float* bk  = (const float*)d_in[5];
    const float* Wv  = (const float*)d_in[6];   const float* bv  = (const float*)d_in[7];
    const float* Wo  = (const float*)d_in[8];   const float* bo  = (const float*)d_in[9];
    const float* g1  = (const float*)d_in[10];  const float* b1  = (const float*)d_in[11];
    const float* W1  = (const float*)d_in[12];  const float* bf1 = (const float*)d_in[13];
    const float* W2  = (const float*)d_in[14];  const float* bf2 = (const float*)d_in[15];
    const float* g2  = (const float*)d_in[16];  const float* b2  = (const float*)d_in[17];
    const float* Wh  = (const float*)d_in[18];  const float* bh  = (const float*)d_in[19];
    float* out = (float*)d_out;

    float *p_h, *p_q, *p_k, *p_v, *p_z, *p_xt;
    cudaGetSymbolAddress((void**)&p_h,  g_h);
    cudaGetSymbolAddress((void**)&p_q,  g_q);
    cudaGetSymbolAddress((void**)&p_k,  g_k);
    cudaGetSymbolAddress((void**)&p_v,  g_v);
    cudaGetSymbolAddress((void**)&p_z,  g_z);
    cudaGetSymbolAddress((void**)&p_xt, g_xt);

    cudaFuncSetAttribute(attn_mma_kernel,
                         cudaFuncAttributeMaxDynamicSharedMemorySize, ATT_SMEM);

    // CSR build: counters are self-restoring (count adds, fill subtracts)
    count_kernel<<<NNZZ / 1024, 256>>>(edge);
    scan_kernel<<<2, 1024>>>();
    fill_kernel<<<NNZZ / 1024, 256>>>(edge);

    QKVArgs qkv;
    qkv.W[0] = Wq; qkv.W[1] = Wk; qkv.W[2] = Wv;
    qkv.b[0] = bq; qkv.b[1] = bk; qkv.b[2] = bv;
    qkv.C[0] = p_q; qkv.C[1] = p_k; qkv.C[2] = p_v;

    const float* hin = x;    // layer 0 reads input directly (no copy)
    for (int L = 0; L < 2; L++) {
        gemm_qkv_kernel<<<dim3(DD / 64, NN / 32, 3), 128>>>(hin, qkv);
        attn_mma_kernel<<<dim3(NN / 128, HH, SP), 256, ATT_SMEM>>>(p_q, p_k, p_v);
        gemm_ln_kernel<<<NN / 16, 128>>>(nullptr, Wo, bo, hin, g1, b1, p_h, DD, 1);
        run_gemm(p_h, W1, bf1, p_z, NN, DD, FFD, 1);
        gemm_ln_kernel<<<NN / 16, 128>>>(p_z, W2, bf2, p_h, g2, b2, p_h, FFD, 0);
        hin = p_h;
    }

    // HypergraphConv
    run_gemm(p_h, Wh, nullptr, p_xt, NN, DD, DD, 0);
    gather_e_kernel<<<NEE, 128>>>(p_xt);
    gather_out_kernel<<<NN, 128>>>(out, bh);
}

// round 17
// speedup vs baseline: 1.5642x; 1.5642x over previous
#include <cuda_runtime.h>
#include <math.h>
#include <stdint.h>

#define NN    4096
#define DD    128
#define HH    2
#define DHH   64
#define FFD   256
#define NEE   2048
#define NNZZ  65536
#define SP    4           // attention key splits
#define LN_EPS 1e-5f

// ---------------- scratch (static device globals; no allocation) ----------------
__device__ float g_h [NN*DD];
__device__ float g_q [NN*DD];
__device__ float g_k [NN*DD];
__device__ float g_v [NN*DD];
__device__ float g_z [NN*FFD];
__device__ float g_xt[NN*DD];
__device__ float g_e [NEE*DD];
__device__ float g_pO[SP*NN*DD];      // unnormalized split outputs
__device__ float g_pl[SP*HH*NN];      // split row sums
// CSR scratch. cnt arrays are SELF-RESTORING: count adds each member once,
// fill subtracts each member once -> exactly 0 at the end of every call.
__device__ int g_he_cnt[NEE];
__device__ int g_n_cnt [NN];
__device__ int g_he_off[NEE + 1];
__device__ int g_n_off [NN + 1];
__device__ int g_he_nodes[NNZZ];
__device__ int g_n_he    [NNZZ];

// ---------------- CSR build ----------------
__global__ void count_kernel(const int* __restrict__ edge)
{
    int base = blockIdx.x * 1024 + threadIdx.x;
    int n0 = edge[base], n1 = edge[base + 256], n2 = edge[base + 512], n3 = edge[base + 768];
    int h0 = edge[NNZZ + base],       h1 = edge[NNZZ + base + 256];
    int h2 = edge[NNZZ + base + 512], h3 = edge[NNZZ + base + 768];
    atomicAdd(&g_n_cnt[n0], 1);  atomicAdd(&g_n_cnt[n1], 1);
    atomicAdd(&g_n_cnt[n2], 1);  atomicAdd(&g_n_cnt[n3], 1);
    atomicAdd(&g_he_cnt[h0], 1); atomicAdd(&g_he_cnt[h1], 1);
    atomicAdd(&g_he_cnt[h2], 1); atomicAdd(&g_he_cnt[h3], 1);
}

__global__ void __launch_bounds__(1024) scan_kernel()
{
    __shared__ int part[1024];
    const int* cnt = blockIdx.x == 0 ? g_he_cnt : g_n_cnt;
    int*       off = blockIdx.x == 0 ? g_he_off : g_n_off;
    const int  n   = blockIdx.x == 0 ? NEE : NN;
    const int  per = n / 1024;
    const int tid  = threadIdx.x;
    const int base = tid * per;

    int s = 0;
    for (int i = 0; i < per; i++) s += cnt[base + i];
    part[tid] = s;
    __syncthreads();
    for (int d = 1; d < 1024; d <<= 1) {
        int v = (tid >= d) ? part[tid - d] : 0;
        __syncthreads();
        part[tid] += v;
        __syncthreads();
    }
    int run = tid ? part[tid - 1] : 0;
    for (int i = 0; i < per; i++) { off[base + i] = run; run += cnt[base + i]; }
    if (tid == 1023) off[n] = run;
}

__global__ void fill_kernel(const int* __restrict__ edge)
{
    int base = blockIdx.x * 1024 + threadIdx.x;
    int n0 = edge[base], n1 = edge[base + 256], n2 = edge[base + 512], n3 = edge[base + 768];
    int h0 = edge[NNZZ + base],       h1 = edge[NNZZ + base + 256];
    int h2 = edge[NNZZ + base + 512], h3 = edge[NNZZ + base + 768];

    int p0 = atomicAdd(&g_he_cnt[h0], -1);
    int p1 = atomicAdd(&g_he_cnt[h1], -1);
    int p2 = atomicAdd(&g_he_cnt[h2], -1);
    int p3 = atomicAdd(&g_he_cnt[h3], -1);
    int q0 = atomicAdd(&g_n_cnt[n0], -1);
    int q1 = atomicAdd(&g_n_cnt[n1], -1);
    int q2 = atomicAdd(&g_n_cnt[n2], -1);
    int q3 = atomicAdd(&g_n_cnt[n3], -1);

    g_he_nodes[g_he_off[h0] + p0 - 1] = n0;
    g_he_nodes[g_he_off[h1] + p1 - 1] = n1;
    g_he_nodes[g_he_off[h2] + p2 - 1] = n2;
    g_he_nodes[g_he_off[h3] + p3 - 1] = n3;
    g_n_he[g_n_off[n0] + q0 - 1] = h0;
    g_n_he[g_n_off[n1] + q1 - 1] = h1;
    g_n_he[g_n_off[n2] + q2 - 1] = h2;
    g_n_he[g_n_off[n3] + q3 - 1] = h3;
}

// ---------------- tf32 mma helpers ----------------
__device__ __forceinline__ uint32_t f2tf(float f)
{
    uint32_t r;
    asm("cvt.rna.tf32.f32 %0, %1;" : "=r"(r) : "f"(f));
    return r;
}

__device__ __forceinline__ void mma_tf32(float c[4], const uint32_t a[4],
                                         uint32_t b0, uint32_t b1)
{
    asm volatile(
        "mma.sync.aligned.m16n8k8.row.col.f32.tf32.tf32.f32 "
        "{%0,%1,%2,%3}, {%4,%5,%6,%7}, {%8,%9}, {%0,%1,%2,%3};"
        : "+f"(c[0]), "+f"(c[1]), "+f"(c[2]), "+f"(c[3])
        : "r"(a[0]), "r"(a[1]), "r"(a[2]), "r"(a[3]), "r"(b0), "r"(b1));
}

// ---------------- tf32 GEMM body: 32x64 tile, 4 warps (2x2), K-chunk 32 -------
#define APAD 36
#define BPAD 72

__device__ __forceinline__ void gemm_body(
    uint32_t* As, uint32_t* Bs,
    const float* __restrict__ A, const float* __restrict__ W,
    const float* __restrict__ bias, float* __restrict__ C,
    int K, int Nn, int mode)
{
    const int tid  = threadIdx.x;
    const int wid  = tid >> 5;
    const int lane = tid & 31;
    const int g    = lane >> 2;
    const int qr   = lane & 3;
    const int wr   = wid >> 1;
    const int wc   = wid & 1;
    const int m0   = blockIdx.y * 32;
    const int n0   = blockIdx.x * 64;
    const int row0 = m0 + wr * 16;
    const int cb   = wc * 32;

    const int ar0 = tid >> 3,  ac0 = tid & 7;
    const int ar1 = (tid + 128) >> 3, ac1 = (tid + 128) & 7;
    const int br0 = tid >> 4,  bc0 = tid & 15;
    const int br1 = (tid + 128) >> 4, bc1 = (tid + 128) & 15;
    const int br2 = (tid + 256) >> 4, bc2 = (tid + 256) & 15;
    const int br3 = (tid + 384) >> 4, bc3 = (tid + 384) & 15;

    float acc[4][4];
    #pragma unroll
    for (int nt = 0; nt < 4; nt++)
        #pragma unroll
        for (int i = 0; i < 4; i++) acc[nt][i] = 0.f;

    float4 ar[2], br[4];
    ar[0] = *(const float4*)&A[(m0 + ar0) * K + ac0 * 4];
    ar[1] = *(const float4*)&A[(m0 + ar1) * K + ac1 * 4];
    br[0] = *(const float4*)&W[br0 * Nn + n0 + bc0 * 4];
    br[1] = *(const float4*)&W[br1 * Nn + n0 + bc1 * 4];
    br[2] = *(const float4*)&W[br2 * Nn + n0 + bc2 * 4];
    br[3] = *(const float4*)&W[br3 * Nn + n0 + bc3 * 4];

    for (int k0 = 0; k0 < K; k0 += 32) {
        *(uint4*)&As[ar0 * APAD + ac0 * 4] =
            make_uint4(f2tf(ar[0].x), f2tf(ar[0].y), f2tf(ar[0].z), f2tf(ar[0].w));
        *(uint4*)&As[ar1 * APAD + ac1 * 4] =
            make_uint4(f2tf(ar[1].x), f2tf(ar[1].y), f2tf(ar[1].z), f2tf(ar[1].w));
        *(uint4*)&Bs[br0 * BPAD + bc0 * 4] =
            make_uint4(f2tf(br[0].x), f2tf(br[0].y), f2tf(br[0].z), f2tf(br[0].w));
        *(uint4*)&Bs[br1 * BPAD + bc1 * 4] =
            make_uint4(f2tf(br[1].x), f2tf(br[1].y), f2tf(br[1].z), f2tf(br[1].w));
        *(uint4*)&Bs[br2 * BPAD + bc2 * 4] =
            make_uint4(f2tf(br[2].x), f2tf(br[2].y), f2tf(br[2].z), f2tf(br[2].w));
        *(uint4*)&Bs[br3 * BPAD + bc3 * 4] =
            make_uint4(f2tf(br[3].x), f2tf(br[3].y), f2tf(br[3].z), f2tf(br[3].w));
        __syncthreads();

        if (k0 + 32 < K) {
            ar[0] = *(const float4*)&A[(m0 + ar0) * K + k0 + 32 + ac0 * 4];
            ar[1] = *(const float4*)&A[(m0 + ar1) * K + k0 + 32 + ac1 * 4];
            br[0] = *(const float4*)&W[(k0 + 32 + br0) * Nn + n0 + bc0 * 4];
            br[1] = *(const float4*)&W[(k0 + 32 + br1) * Nn + n0 + bc1 * 4];
            br[2] = *(const float4*)&W[(k0 + 32 + br2) * Nn + n0 + bc2 * 4];
            br[3] = *(const float4*)&W[(k0 + 32 + br3) * Nn + n0 + bc3 * 4];
        }

        #pragma unroll
        for (int kt = 0; kt < 4; kt++) {
            uint32_t a[4];
            a[0] = As[(wr * 16 + g    ) * APAD + kt * 8 + qr    ];
            a[1] = As[(wr * 16 + g + 8) * APAD + kt * 8 + qr    ];
            a[2] = As[(wr * 16 + g    ) * APAD + kt * 8 + qr + 4];
            a[3] = As[(wr * 16 + g + 8) * APAD + kt * 8 + qr + 4];
            #pragma unroll
            for (int nt = 0; nt < 4; nt++) {
                uint32_t b0 = Bs[(kt * 8 + qr    ) * BPAD + cb + nt * 8 + g];
                uint32_t b1 = Bs[(kt * 8 + qr + 4) * BPAD + cb + nt * 8 + g];
                mma_tf32(acc[nt], a, b0, b1);
            }
        }
        __syncthreads();
    }

    #pragma unroll
    for (int nt = 0; nt < 4; nt++) {
        int col = n0 + cb + nt * 8 + 2 * qr;
        float b0v = bias ? bias[col]     : 0.f;
        float b1v = bias ? bias[col + 1] : 0.f;
        float c0 = acc[nt][0] + b0v, c1 = acc[nt][1] + b1v;
        float c2 = acc[nt][2] + b0v, c3 = acc[nt][3] + b1v;
        if (mode == 1) {
            c0 = 1.f / (1.f + __expf(-c0));
            c1 = 1.f / (1.f + __expf(-c1));
            c2 = 1.f / (1.f + __expf(-c2));
            c3 = 1.f / (1.f + __expf(-c3));
        }
        *(float2*)&C[(row0 + g    ) * Nn + col] = make_float2(c0, c1);
        *(float2*)&C[(row0 + g + 8) * Nn + col] = make_float2(c2, c3);
    }
}

__global__ void __launch_bounds__(128)
gemm_mma_kernel(const float* __restrict__ A, const float* __restrict__ W,
                const float* __restrict__ bias, float* __restrict__ C,
                int K, int Nn, int mode)
{
    __shared__ uint32_t As[32 * APAD];
    __shared__ uint32_t Bs[32 * BPAD];
    gemm_body(As, Bs, A, W, bias, C, K, Nn, mode);
}

struct QKVArgs {
    const float* W[3];
    const float* b[3];
    float*       C[3];
};

__global__ void __launch_bounds__(128)
gemm_qkv_kernel(const float* __restrict__ A, QKVArgs args)
{
    __shared__ uint32_t As[32 * APAD];
    __shared__ uint32_t Bs[32 * BPAD];
    int z = blockIdx.z;
    gemm_body(As, Bs, A, args.W[z], args.b[z], args.C[z], DD, DD, 0);
}

// ---------------- GEMM fused with residual + LayerNorm -----------------------
// C[m,:] = LN(resid[m,:] + Aeff[m,:]@W + bias) * lng + lnb
// combine=1: Aeff = attention output assembled inline from g_pO/g_pl (K must be DD)
#define BPAD2 136
__global__ void __launch_bounds__(128)
gemm_ln_kernel(const float* __restrict__ A, const float* __restrict__ W,
               const float* __restrict__ bias, const float* __restrict__ resid,
               const float* __restrict__ lng, const float* __restrict__ lnb,
               float* __restrict__ C, int K, int combine)
{
    __shared__ uint32_t As[16 * APAD];
    __shared__ uint32_t Bs[32 * BPAD2];
    __shared__ float redS[16][4];
    __shared__ float redQ[16][4];

    const int tid  = threadIdx.x;
    const int wid  = tid >> 5;
    const int lane = tid & 31;
    const int g    = lane >> 2;
    const int qr   = lane & 3;
    const int m0   = blockIdx.x * 16;
    const int cb   = wid * 32;

    const int arow = tid >> 3, acol = tid & 7;
    const int aRow = m0 + arow;

    float inv_l[2] = {0.f, 0.f};
    if (combine) {
        #pragma unroll
        for (int h = 0; h < HH; h++) {
            float l = 0.f;
            #pragma unroll
            for (int s = 0; s < SP; s++) l += g_pl[(s * HH + h) * NN + aRow];
            inv_l[h] = 1.f / l;
        }
    }

    float acc[4][4];
    #pragma unroll
    for (int nt = 0; nt < 4; nt++)
        #pragma unroll
        for (int i = 0; i < 4; i++) acc[nt][i] = 0.f;

    float4 ar, br[8];
    #define LOAD_A(K0) do {                                              \
        int col = (K0) + acol * 4;                                       \
        if (combine) {                                                   \
            float4 o = make_float4(0.f, 0.f, 0.f, 0.f);                  \
            _Pragma("unroll")                                            \
            for (int s = 0; s < SP; s++) {                               \
                float4 p = *(const float4*)&g_pO[s * NN * DD + aRow * DD + col]; \
                o.x += p.x; o.y += p.y; o.z += p.z; o.w += p.w;          \
            }                                                            \
            float il = inv_l[col >> 6];                                  \
            ar = make_float4(o.x * il, o.y * il, o.z * il, o.w * il);    \
        } else {                                                         \
            ar = *(const float4*)&A[aRow * K + col];                     \
        }                                                                \
    } while (0)

    LOAD_A(0);
    #pragma unroll
    for (int it = 0; it < 8; it++) {
        int f = tid + it * 128;
        br[it] = *(const float4*)&W[(f >> 5) * DD + (f & 31) * 4];
    }

    for (int k0 = 0; k0 < K; k0 += 32) {
        *(uint4*)&As[arow * APAD + acol * 4] =
            make_uint4(f2tf(ar.x), f2tf(ar.y), f2tf(ar.z), f2tf(ar.w));
        #pragma unroll
        for (int it = 0; it < 8; it++) {
            int f = tid + it * 128;
            *(uint4*)&Bs[(f >> 5) * BPAD2 + (f & 31) * 4] =
                make_uint4(f2tf(br[it].x), f2tf(br[it].y), f2tf(br[it].z), f2tf(br[it].w));
        }
        __syncthreads();

        if (k0 + 32 < K) {
            LOAD_A(k0 + 32);
            #pragma unroll
            for (int it = 0; it < 8; it++) {
                int f = tid + it * 128;
                br[it] = *(const float4*)&W[(k0 + 32 + (f >> 5)) * DD + (f & 31) * 4];
            }
        }

        #pragma unroll
        for (int kt = 0; kt < 4; kt++) {
            uint32_t a[4];
            a[0] = As[(g    ) * APAD + kt * 8 + qr    ];
            a[1] = As[(g + 8) * APAD + kt * 8 + qr    ];
            a[2] = As[(g    ) * APAD + kt * 8 + qr + 4];
            a[3] = As[(g + 8) * APAD + kt * 8 + qr + 4];
            #pragma unroll
            for (int nt = 0; nt < 4; nt++) {
                uint32_t b0 = Bs[(kt * 8 + qr    ) * BPAD2 + cb + nt * 8 + g];
                uint32_t b1 = Bs[(kt * 8 + qr + 4) * BPAD2 + cb + nt * 8 + g];
                mma_tf32(acc[nt], a, b0, b1);
            }
        }
        __syncthreads();
    }

    float s_lo = 0.f, q_lo = 0.f, s_hi = 0.f, q_hi = 0.f;
    #pragma unroll
    for (int nt = 0; nt < 4; nt++) {
        int col = cb + nt * 8 + 2 * qr;
        float2 bv = *(const float2*)&bias[col];
        float2 r0 = *(const float2*)&resid[(m0 + g    ) * DD + col];
        float2 r1 = *(const float2*)&resid[(m0 + g + 8) * DD + col];
        float x0 = acc[nt][0] + bv.x + r0.x;
        float x1 = acc[nt][1] + bv.y + r0.y;
        float x2 = acc[nt][2] + bv.x + r1.x;
        float x3 = acc[nt][3] + bv.y + r1.y;
        acc[nt][0] = x0; acc[nt][1] = x1; acc[nt][2] = x2; acc[nt][3] = x3;
        s_lo += x0 + x1;  q_lo += x0 * x0 + x1 * x1;
        s_hi += x2 + x3;  q_hi += x2 * x2 + x3 * x3;
    }
    s_lo += __shfl_xor_sync(0xffffffffu, s_lo, 1);
    s_lo += __shfl_xor_sync(0xffffffffu, s_lo, 2);
    q_lo += __shfl_xor_sync(0xffffffffu, q_lo, 1);
    q_lo += __shfl_xor_sync(0xffffffffu, q_lo, 2);
    s_hi += __shfl_xor_sync(0xffffffffu, s_hi, 1);
    s_hi += __shfl_xor_sync(0xffffffffu, s_hi, 2);
    q_hi += __shfl_xor_sync(0xffffffffu, q_hi, 1);
    q_hi += __shfl_xor_sync(0xffffffffu, q_hi, 2);
    if (qr == 0) {
        redS[g][wid]     = s_lo;  redQ[g][wid]     = q_lo;
        redS[g + 8][wid] = s_hi;  redQ[g + 8][wid] = q_hi;
    }
    __syncthreads();

    float sl = redS[g][0] + redS[g][1] + redS[g][2] + redS[g][3];
    float ql = redQ[g][0] + redQ[g][1] + redQ[g][2] + redQ[g][3];
    float sh = redS[g + 8][0] + redS[g + 8][1] + redS[g + 8][2] + redS[g + 8][3];
    float qh = redQ[g + 8][0] + redQ[g + 8][1] + redQ[g + 8][2] + redQ[g + 8][3];
    float mean_lo = sl * (1.f / 128.f);
    float mean_hi = sh * (1.f / 128.f);
    float rstd_lo = rsqrtf(ql * (1.f / 128.f) - mean_lo * mean_lo + LN_EPS);
    float rstd_hi = rsqrtf(qh * (1.f / 128.f) - mean_hi * mean_hi + LN_EPS);

    #pragma unroll
    for (int nt = 0; nt < 4; nt++) {
        int col = cb + nt * 8 + 2 * qr;
        float2 gg = *(const float2*)&lng[col];
        float2 bb = *(const float2*)&lnb[col];
        float2 o0, o1;
        o0.x = (acc[nt][0] - mean_lo) * rstd_lo * gg.x + bb.x;
        o0.y = (acc[nt][1] - mean_lo) * rstd_lo * gg.y + bb.y;
        o1.x = (acc[nt][2] - mean_hi) * rstd_hi * gg.x + bb.x;
        o1.y = (acc[nt][3] - mean_hi) * rstd_hi * gg.y + bb.y;
        *(float2*)&C[(m0 + g    ) * DD + col] = o0;
        *(float2*)&C[(m0 + g + 8) * DD + col] = o1;
    }
}

// ---------------- tensor-core flash attention, split-K, 128 queries/CTA -------
// 8 warps, each owns 16 query rows across the full 64 key/output columns.
// NO K/V register prefetch: it pushed regs past the 2-CTA/SM boundary (R13 regression).
#define KPAD 68
#define VPAD 72
#define ATT_SMEM ((64*KPAD + 64*VPAD + 8*16*KPAD) * 4)   // 70656 bytes

__global__ void __launch_bounds__(256)
attn_mma_kernel(const float* __restrict__ q, const float* __restrict__ k,
                const float* __restrict__ v)
{
    extern __shared__ uint32_t smu[];
    uint32_t* Ks = smu;
    uint32_t* Vs = smu + 64 * KPAD;
    uint32_t* Ps = smu + 64 * KPAD + 64 * VPAD + (threadIdx.x >> 5) * (16 * KPAD);

    const int tid  = threadIdx.x;
    const int wid  = tid >> 5;
    const int lane = tid & 31;
    const int h    = blockIdx.y;
    const int s    = blockIdx.z;
    const int q0   = blockIdx.x * 128;
    const int g    = lane >> 2;
    const int qr   = lane & 3;
    const int base = h * DHH;
    const int row0 = q0 + wid * 16;
    const int kb   = s * (NN / SP);
    const int ke   = kb + (NN / SP);

    uint32_t qa[8][4];
    #pragma unroll
    for (int kt = 0; kt < 8; kt++) {
        qa[kt][0] = f2tf(q[(row0 + g    ) * DD + base + kt * 8 + qr    ] * 0.125f);
        qa[kt][1] = f2tf(q[(row0 + g + 8) * DD + base + kt * 8 + qr    ] * 0.125f);
        qa[kt][2] = f2tf(q[(row0 + g    ) * DD + base + kt * 8 + qr + 4] * 0.125f);
        qa[kt][3] = f2tf(q[(row0 + g + 8) * DD + base + kt * 8 + qr + 4] * 0.125f);
    }

    float oc[8][4];
    #pragma unroll
    for (int nt = 0; nt < 8; nt++)
        #pragma unroll
        for (int i = 0; i < 4; i++) oc[nt][i] = 0.f;
    float l_lo = 0.f, l_hi = 0.f;

    for (int j0 = kb; j0 < ke; j0 += 64) {
        // K/V 64x64 tiles: 1024 float4 over 256 threads
        #pragma unroll
        for (int it = 0; it < 4; it++) {
            int idx = tid + it * 256;
            int row = idx >> 4, c4 = idx & 15;
            float4 kf = *(const float4*)&k[(j0 + row) * DD + base + c4 * 4];
            float4 vf = *(const float4*)&v[(j0 + row) * DD + base + c4 * 4];
            *(uint4*)&Ks[row * KPAD + c4 * 4] =
                make_uint4(f2tf(kf.x), f2tf(kf.y), f2tf(kf.z), f2tf(kf.w));
            *(uint4*)&Vs[row * VPAD + c4 * 4] =
                make_uint4(f2tf(vf.x), f2tf(vf.y), f2tf(vf.z), f2tf(vf.w));
        }
        __syncthreads();

        // S = Q @ K^T (16 x 64 per warp)
        float sc[8][4];
        #pragma unroll
        for (int nt = 0; nt < 8; nt++)
            #pragma unroll
            for (int i = 0; i < 4; i++) sc[nt][i] = 0.f;

        #pragma unroll
        for (int nt = 0; nt < 8; nt++) {
            #pragma unroll
            for (int kt = 0; kt < 8; kt++) {
                uint32_t b0 = Ks[(nt * 8 + g) * KPAD + kt * 8 + qr    ];
                uint32_t b1 = Ks[(nt * 8 + g) * KPAD + kt * 8 + qr + 4];
                mma_tf32(sc[nt], qa[kt], b0, b1);
            }
        }

        // P = exp(S); warp-local row sums; stash P in per-warp smem
        float s_lo = 0.f, s_hi = 0.f;
        #pragma unroll
        for (int nt = 0; nt < 8; nt++) {
            float e0 = __expf(sc[nt][0]), e1 = __expf(sc[nt][1]);
            float e2 = __expf(sc[nt][2]), e3 = __expf(sc[nt][3]);
            s_lo += e0 + e1;
            s_hi += e2 + e3;
            *(uint2*)&Ps[ g      * KPAD + nt * 8 + 2 * qr] = make_uint2(f2tf(e0), f2tf(e1));
            *(uint2*)&Ps[(g + 8) * KPAD + nt * 8 + 2 * qr] = make_uint2(f2tf(e2), f2tf(e3));
        }
        s_lo += __shfl_xor_sync(0xffffffffu, s_lo, 1);
        s_lo += __shfl_xor_sync(0xffffffffu, s_lo, 2);
        s_hi += __shfl_xor_sync(0xffffffffu, s_hi, 1);
        s_hi += __shfl_xor_sync(0xffffffffu, s_hi, 2);
        l_lo += s_lo;
        l_hi += s_hi;
        __syncwarp();

        // O += P @ V
        #pragma unroll
        for (int kt = 0; kt < 8; kt++) {
            uint32_t a[4];
            a[0] = Ps[ g      * KPAD + kt * 8 + qr    ];
            a[1] = Ps[(g + 8) * KPAD + kt * 8 + qr    ];
            a[2] = Ps[ g      * KPAD + kt * 8 + qr + 4];
            a[3] = Ps[(g + 8) * KPAD + kt * 8 + qr + 4];
            #pragma unroll
            for (int nt = 0; nt < 8; nt++) {
                uint32_t b0 = Vs[(kt * 8 + qr    ) * VPAD + nt * 8 + g];
                uint32_t b1 = Vs[(kt * 8 + qr + 4) * VPAD + nt * 8 + g];
                mma_tf32(oc[nt], a, b0, b1);
            }
        }
        __syncthreads();   // protect Ks/Vs before next iteration's loads
    }

    if (qr == 0) {   // warp-complete row sums
        g_pl[(s * HH + h) * NN + row0 + g]     = l_lo;
        g_pl[(s * HH + h) * NN + row0 + g + 8] = l_hi;
    }

    float* pO = &g_pO[s * NN * DD];
    #pragma unroll
    for (int nt = 0; nt < 8; nt++) {
        *(float2*)&pO[(row0 + g    ) * DD + base + nt * 8 + 2 * qr] =
            make_float2(oc[nt][0], oc[nt][1]);
        *(float2*)&pO[(row0 + g + 8) * DD + base + nt * 8 + 2 * qr] =
            make_float2(oc[nt][2], oc[nt][3]);
    }
}

// ---------------- hypergraph gathers (atomic-free via CSR) --------------------
__global__ void __launch_bounds__(128)
gather_e_kernel(const float* __restrict__ xt)
{
    __shared__ int mem[128];
    const int he = blockIdx.x;
    const int d  = threadIdx.x;
    const int beg = g_he_off[he], end = g_he_off[he + 1];

    float s = 0.f;
    for (int base = beg; base < end; base += 128) {
        int cnt = min(128, end - base);
        __syncthreads();
        if (d < cnt) mem[d] = g_he_nodes[base + d];
        __syncthreads();
        for (int i = 0; i < cnt; i++) s += xt[mem[i] * DD + d];
    }
    float binv = (end > beg) ? 1.f / (float)(end - beg) : 0.f;
    g_e[he * DD + d] = s * binv;
}

__global__ void __launch_bounds__(128)
gather_out_kernel(float* __restrict__ out, const float* __restrict__ bh)
{
    __shared__ int mem[128];
    const int n = blockIdx.x;
    const int d = threadIdx.x;
    const int beg = g_n_off[n], end = g_n_off[n + 1];

    float s = 0.f;
    for (int base = beg; base < end; base += 128) {
        int cnt = min(128, end - base);
        __syncthreads();
        if (d < cnt) mem[d] = g_n_he[base + d];
        __syncthreads();
        for (int i = 0; i < cnt; i++) s += g_e[mem[i] * DD + d];
    }
    float dinv = (end > beg) ? 1.f / (float)(end - beg) : 0.f;
    out[n * DD + d] = fmaxf(s * dinv + bh[d], 0.f);
}

// ---------------- host ----------------
static inline void run_gemm(const float* A, const float* W, const float* bias, float* C,
                            int M, int K, int Nn, int mode)
{
    dim3 grid(Nn / 64, M / 32);
    gemm_mma_kernel<<<grid, 128>>>(A, W, bias, C, K, Nn, mode);
}

extern "C" void kernel_launch(void* const* d_in, const int* in_sizes, int n_in,
                              void* d_out, int out_size)
{
    const float* x    = (const float*)d_in[0];
    const int*   edge = (const int*)d_in[1];      // int32: JAX x64 disabled
    const float* Wq  = (const float*)d_in[2];   const float* bq  = (const float*)d_in[3];
    const float* Wk  = (const float*)d_in[4];   const float* bk  = (const float*)d_in[5];
    const float* Wv  = (const float*)d_in[6];   const float* bv  = (const float*)d_in[7];
    const float* Wo  = (const float*)d_in[8];   const float* bo  = (const float*)d_in[9];
    const float* g1  = (const float*)d_in[10];  const float* b1  = (const float*)d_in[11];
    const float* W1  = (const float*)d_in[12];  const float* bf1 = (const float*)d_in[13];
    const float* W2  = (const float*)d_in[14];  const float* bf2 = (const float*)d_in[15];
    const float* g2  = (const float*)d_in[16];  const float* b2  = (const float*)d_in[17];
    const float* Wh  = (const float*)d_in[18];  const float* bh  = (const float*)d_in[19];
    float* out = (float*)d_out;

    float *p_h, *p_q, *p_k, *p_v, *p_z, *p_xt;
    cudaGetSymbolAddress((void**)&p_h,  g_h);
    cudaGetSymbolAddress((void**)&p_q,  g_q);
    cudaGetSymbolAddress((void**)&p_k,  g_k);
    cudaGetSymbolAddress((void**)&p_v,  g_v);
    cudaGetSymbolAddress((void**)&p_z,  g_z);
    cudaGetSymbolAddress((void**)&p_xt, g_xt);

    cudaFuncSetAttribute(attn_mma_kernel,
                         cudaFuncAttributeMaxDynamicSharedMemorySize, ATT_SMEM);

    // CSR build: counters are self-restoring (count adds, fill subtracts)
    count_kernel<<<NNZZ / 1024, 256>>>(edge);
    scan_kernel<<<2, 1024>>>();
    fill_kernel<<<NNZZ / 1024, 256>>>(edge);

    QKVArgs qkv;
    qkv.W[0] = Wq; qkv.W[1] = Wk; qkv.W[2] = Wv;
    qkv.b[0] = bq; qkv.b[1] = bk; qkv.b[2] = bv;
    qkv.C[0] = p_q; qkv.C[1] = p_k; qkv.C[2] = p_v;

    const float* hin = x;    // layer 0 reads input directly (no copy)
    for (int L = 0; L < 2; L++) {
        gemm_qkv_kernel<<<dim3(DD / 64, NN / 32, 3), 128>>>(hin, qkv);
        attn_mma_kernel<<<dim3(NN / 128, HH, SP), 256, ATT_SMEM>>>(p_q, p_k, p_v);
        gemm_ln_kernel<<<NN / 16, 128>>>(nullptr, Wo, bo, hin, g1, b1, p_h, DD, 1);
        run_gemm(p_h, W1, bf1, p_z, NN, DD, FFD, 1);
        gemm_ln_kernel<<<NN / 16, 128>>>(p_z, W2, bf2, p_h, g2, b2, p_h, FFD, 0);
        hin = p_h;
    }

    // HypergraphConv
    run_gemm(p_h, Wh, nullptr, p_xt, NN, DD, DD, 0);
    gather_e_kernel<<<NEE, 128>>>(p_xt);
    gather_out_kernel<<<NN, 128>>>(out, bh);
}